// round 12
// baseline (speedup 1.0000x reference)
#include <cuda_runtime.h>
#include <cstdint>

namespace {
constexpr int B = 64, T = 512, C = 384, H = 64;
constexpr int BT = B * T;
}

// Scratch for projected q, k, v (fp32, [B*T, H] each). Static device arrays.
__device__ float g_q[BT * H];
__device__ float g_k[BT * H];
__device__ float g_v[BT * H];

// ---------------------------------------------------------------------------
// helpers
// ---------------------------------------------------------------------------
__device__ __forceinline__ uint32_t f2tf(float f) {
  uint32_t u;
  asm("cvt.rna.tf32.f32 %0, %1;" : "=r"(u) : "f"(f));
  return u;
}

// D = A(16x8,row) * B(8x8,col) + C, tf32 inputs, fp32 accum.
__device__ __forceinline__ void mma_tf32(float* d, const uint32_t* a,
                                         uint32_t b0, uint32_t b1) {
  asm("mma.sync.aligned.m16n8k8.row.col.f32.tf32.tf32.f32 "
      "{%0,%1,%2,%3}, {%4,%5,%6,%7}, {%8,%9}, {%0,%1,%2,%3};"
      : "+f"(d[0]), "+f"(d[1]), "+f"(d[2]), "+f"(d[3])
      : "r"(a[0]), "r"(a[1]), "r"(a[2]), "r"(a[3]), "r"(b0), "r"(b1));
}

__device__ __forceinline__ void cp_async16(uint32_t smem_byte,
                                           const void* gptr) {
  asm volatile("cp.async.ca.shared.global [%0], [%1], 16;\n" ::"r"(smem_byte),
               "l"(gptr));
}
#define CP_COMMIT() asm volatile("cp.async.commit_group;\n" ::: "memory")
#define CP_WAIT1() asm volatile("cp.async.wait_group 1;\n" ::: "memory")

__device__ __forceinline__ uint32_t smem_u32(const void* p) {
  return (uint32_t)__cvta_generic_to_shared(p);
}

// ---------------------------------------------------------------------------
// Kernel 1: fused QKV projection, tf32 mma, cp.async 2-stage pipeline.
// y[32768,192] = x[32768,384] @ [Wq|Wk|Wv][384,192].
// CTA: 128 thr = 4 warps (2M x 2N), CTA tile 64x192, K-chunk 32, 12 chunks.
// Raw fp32 staged; cvt.rna.tf32 at fragment read.
// smem strides: xs=36 (≡4 mod 32), ws=200 (≡8 mod 32) -> conflict-free.
// ---------------------------------------------------------------------------
namespace {
constexpr int XS_STRIDE = 36;
constexpr int WS_STRIDE = 200;
constexpr int X_STAGE_W = 64 * XS_STRIDE;   // 2304 words per stage
constexpr int W_STAGE_W = 32 * WS_STRIDE;   // 6400 words per stage
constexpr int QKV_WR_OFF = 2 * X_STAGE_W;   // 4608
constexpr int QKV_SMEM_W = QKV_WR_OFF + 2 * W_STAGE_W;  // 17408
constexpr int QKV_SMEM_BYTES = QKV_SMEM_W * 4;          // 69632
}

__global__ __launch_bounds__(128, 3) void qkv_mma_kernel(
    const float* __restrict__ x, const float* __restrict__ Wq,
    const float* __restrict__ Wk, const float* __restrict__ Wv) {
  extern __shared__ float qsm[];
  const uint32_t smb = smem_u32(qsm);

  const int row0 = blockIdx.x * 64;
  const int warp = threadIdx.x >> 5;
  const int lane = threadIdx.x & 31;
  const int wm = warp >> 1;  // 0..1 -> rows wm*32..+32
  const int wn = warp & 1;   // 0..1 -> cols wn*96..+96
  const int lr = lane >> 2;  // 0..7
  const int lc = lane & 3;   // 0..3

  // issue cp.asyncs for one K-chunk into stage (chunk&1); always commit.
  auto issue = [&](int chunk) {
    if (chunk < 12) {
      const int s = chunk & 1;
      const int c0 = chunk * 32;
      // x tile [64 x 32]: 512 float4 / 128 thr = 4 each
      const uint32_t xb = smb + (uint32_t)(s * X_STAGE_W) * 4u;
      #pragma unroll
      for (int i = threadIdx.x; i < 512; i += 128) {
        const int r = i >> 3, c4 = i & 7;
        cp_async16(xb + (uint32_t)(r * XS_STRIDE + c4 * 4) * 4u,
                   x + (size_t)(row0 + r) * C + c0 + c4 * 4);
      }
      // W tile [32 x 192]: 1536 float4 / 128 thr = 12 each
      const uint32_t wb = smb + (uint32_t)(QKV_WR_OFF + s * W_STAGE_W) * 4u;
      #pragma unroll
      for (int i = threadIdx.x; i < 1536; i += 128) {
        const int k = i / 48, n4 = i % 48;
        const float* Wsrc = (n4 < 16) ? Wq : (n4 < 32) ? Wk : Wv;
        cp_async16(wb + (uint32_t)(k * WS_STRIDE + n4 * 4) * 4u,
                   Wsrc + (size_t)(c0 + k) * H + (n4 & 15) * 4);
      }
    }
    CP_COMMIT();
  };

  float acc[2][12][4];
  #pragma unroll
  for (int mt = 0; mt < 2; ++mt)
    #pragma unroll
    for (int nt = 0; nt < 12; ++nt)
      #pragma unroll
      for (int i = 0; i < 4; ++i) acc[mt][nt][i] = 0.f;

  issue(0);
  issue(1);

  for (int chunk = 0; chunk < 12; ++chunk) {
    const int s = chunk & 1;
    CP_WAIT1();
    __syncthreads();

    const float* Xs = qsm + s * X_STAGE_W;
    const float* Ws = qsm + QKV_WR_OFF + s * W_STAGE_W;

    uint32_t af[2][4][4];
    #pragma unroll
    for (int mt = 0; mt < 2; ++mt) {
      const int row = wm * 32 + mt * 16 + lr;
      #pragma unroll
      for (int kk = 0; kk < 4; ++kk) {
        const int col = kk * 8 + lc;
        af[mt][kk][0] = f2tf(Xs[row * XS_STRIDE + col]);
        af[mt][kk][1] = f2tf(Xs[(row + 8) * XS_STRIDE + col]);
        af[mt][kk][2] = f2tf(Xs[row * XS_STRIDE + col + 4]);
        af[mt][kk][3] = f2tf(Xs[(row + 8) * XS_STRIDE + col + 4]);
      }
    }

    #pragma unroll
    for (int nt = 0; nt < 12; ++nt) {
      const int n = wn * 96 + nt * 8 + lr;
      #pragma unroll
      for (int kk = 0; kk < 4; ++kk) {
        const int k = kk * 8 + lc;
        const uint32_t b0 = f2tf(Ws[k * WS_STRIDE + n]);
        const uint32_t b1 = f2tf(Ws[(k + 4) * WS_STRIDE + n]);
        mma_tf32(acc[0][nt], af[0][kk], b0, b1);
        mma_tf32(acc[1][nt], af[1][kk], b0, b1);
      }
    }

    __syncthreads();
    issue(chunk + 2);
  }

  // epilogue: scatter to g_q / g_k / g_v
  #pragma unroll
  for (int mt = 0; mt < 2; ++mt) {
    const int rbase = row0 + wm * 32 + mt * 16 + lr;
    #pragma unroll
    for (int nt = 0; nt < 12; ++nt) {
      const int n0 = wn * 96 + nt * 8 + lc * 2;
      float* dst = (n0 < 64) ? g_q : (n0 < 128) ? g_k : g_v;
      const int nn = n0 & 63;
      *reinterpret_cast<float2*>(&dst[(size_t)rbase * H + nn]) =
          make_float2(acc[mt][nt][0], acc[mt][nt][1]);
      *reinterpret_cast<float2*>(&dst[(size_t)(rbase + 8) * H + nn]) =
          make_float2(acc[mt][nt][2], acc[mt][nt][3]);
    }
  }
}

// ---------------------------------------------------------------------------
// Kernel 2: flash attention, causal, tf32 mma, cp.async 2-stage K/V pipeline.
// Grid (8 qt, 64 b) x 128 thr. Warp w owns q-rows [w*16, w*16+16).
// K/V staged raw fp32 (double-buffered), cvt at fragment read.
// Strides: Qs/Ks/Ps 68 (≡4 mod 32), Vs 72 (≡8 mod 32) -> conflict-free.
// ---------------------------------------------------------------------------
namespace {
constexpr int AQ_OFF = 0;                       // tf32 Q  [64][68]
constexpr int AK_OFF = 64 * 68;                 // raw K   2x[64][68]
constexpr int K_STAGE_W = 64 * 68;              // 4352
constexpr int AV_OFF = AK_OFF + 2 * K_STAGE_W;  // 13056: raw V 2x[64][72]
constexpr int V_STAGE_W = 64 * 72;              // 4608
constexpr int AP_OFF = AV_OFF + 2 * V_STAGE_W;  // 22272: tf32 P [64][68]
constexpr int ATTN_SMEM_W = AP_OFF + 64 * 68;   // 26624
constexpr int ATTN_SMEM_BYTES = ATTN_SMEM_W * 4;  // 106496
}

__global__ __launch_bounds__(128, 2) void attn_mma_kernel(
    float* __restrict__ out) {
  extern __shared__ uint32_t sm[];
  uint32_t* Qs = sm + AQ_OFF;
  const float* Kr = reinterpret_cast<const float*>(sm + AK_OFF);
  const float* Vr = reinterpret_cast<const float*>(sm + AV_OFF);
  uint32_t* Ps = sm + AP_OFF;
  const uint32_t smb = smem_u32(sm);

  const int qt = 7 - (int)blockIdx.x;  // heavy tiles first
  const int b = (int)blockIdx.y;
  const int nkt = qt + 1;
  const int warp = threadIdx.x >> 5;
  const int lane = threadIdx.x & 31;
  const int lr = lane >> 2, lc = lane & 3;
  const int qrow = warp * 16 + lr;

  auto issue = [&](int kt) {
    if (kt < nkt) {
      const int s = kt & 1;
      const float* kg = g_k + ((size_t)b * T + (size_t)kt * 64) * H;
      const float* vg = g_v + ((size_t)b * T + (size_t)kt * 64) * H;
      const uint32_t kb = smb + (uint32_t)(AK_OFF + s * K_STAGE_W) * 4u;
      const uint32_t vb = smb + (uint32_t)(AV_OFF + s * V_STAGE_W) * 4u;
      #pragma unroll
      for (int i = threadIdx.x; i < 1024; i += 128) {
        const int r = i >> 4, c4 = i & 15;
        cp_async16(kb + (uint32_t)(r * 68 + c4 * 4) * 4u, kg + r * 64 + c4 * 4);
        cp_async16(vb + (uint32_t)(r * 72 + c4 * 4) * 4u, vg + r * 64 + c4 * 4);
      }
    }
    CP_COMMIT();
  };

  issue(0);
  issue(1);

  // stage Q (pre-scaled by 1/8), tf32 — overlaps with the cp.asyncs above
  const float* qg = g_q + ((size_t)b * T + (size_t)qt * 64) * H;
  for (int i = threadIdx.x * 4; i < 64 * 64; i += 512) {
    const float4 v = *reinterpret_cast<const float4*>(qg + i);
    const int r = i >> 6, c = i & 63;
    Qs[r * 68 + c] = f2tf(v.x * 0.125f);
    Qs[r * 68 + c + 1] = f2tf(v.y * 0.125f);
    Qs[r * 68 + c + 2] = f2tf(v.z * 0.125f);
    Qs[r * 68 + c + 3] = f2tf(v.w * 0.125f);
  }
  __syncthreads();

  // hoist Q A-fragments (8 k-steps x 4 regs)
  uint32_t aq[8][4];
  #pragma unroll
  for (int kk = 0; kk < 8; ++kk) {
    const int c = kk * 8 + lc;
    aq[kk][0] = Qs[qrow * 68 + c];
    aq[kk][1] = Qs[(qrow + 8) * 68 + c];
    aq[kk][2] = Qs[qrow * 68 + c + 4];
    aq[kk][3] = Qs[(qrow + 8) * 68 + c + 4];
  }

  float m[2] = {-1e30f, -1e30f}, l[2] = {0.f, 0.f};
  float o[8][4];
  #pragma unroll
  for (int nt = 0; nt < 8; ++nt)
    #pragma unroll
    for (int i = 0; i < 4; ++i) o[nt][i] = 0.f;

  for (int kt = 0; kt < nkt; ++kt) {
    const int s = kt & 1;
    CP_WAIT1();
    __syncthreads();
    const float* Ks = Kr + s * K_STAGE_W;
    const float* Vs = Vr + s * V_STAGE_W;

    // S = Q K^T
    float sfr[8][4];
    #pragma unroll
    for (int nt = 0; nt < 8; ++nt)
      #pragma unroll
      for (int i = 0; i < 4; ++i) sfr[nt][i] = 0.f;

    #pragma unroll
    for (int nt = 0; nt < 8; ++nt) {
      const int kv = nt * 8 + lr;
      #pragma unroll
      for (int kk = 0; kk < 8; ++kk) {
        const int h = kk * 8 + lc;
        mma_tf32(sfr[nt], aq[kk], f2tf(Ks[kv * 68 + h]),
                 f2tf(Ks[kv * 68 + h + 4]));
      }
    }

    if (kt == qt) {  // causal mask inside diagonal tile
      #pragma unroll
      for (int nt = 0; nt < 8; ++nt) {
        const int kv0 = nt * 8 + lc * 2;
        if (kv0 > qrow) sfr[nt][0] = -1e30f;
        if (kv0 + 1 > qrow) sfr[nt][1] = -1e30f;
        if (kv0 > qrow + 8) sfr[nt][2] = -1e30f;
        if (kv0 + 1 > qrow + 8) sfr[nt][3] = -1e30f;
      }
    }

    // online softmax per fragment row-group (rows qrow, qrow+8)
    #pragma unroll
    for (int g = 0; g < 2; ++g) {
      float mx = -1e30f;
      #pragma unroll
      for (int nt = 0; nt < 8; ++nt)
        mx = fmaxf(mx, fmaxf(sfr[nt][2 * g], sfr[nt][2 * g + 1]));
      mx = fmaxf(mx, __shfl_xor_sync(0xffffffffu, mx, 1));
      mx = fmaxf(mx, __shfl_xor_sync(0xffffffffu, mx, 2));
      const float mnew = fmaxf(m[g], mx);
      const float alpha = __expf(m[g] - mnew);
      float ls = 0.f;
      #pragma unroll
      for (int nt = 0; nt < 8; ++nt) {
        const float p0 = __expf(sfr[nt][2 * g] - mnew);
        const float p1 = __expf(sfr[nt][2 * g + 1] - mnew);
        sfr[nt][2 * g] = p0;
        sfr[nt][2 * g + 1] = p1;
        ls += p0 + p1;
      }
      ls += __shfl_xor_sync(0xffffffffu, ls, 1);
      ls += __shfl_xor_sync(0xffffffffu, ls, 2);
      m[g] = mnew;
      l[g] = l[g] * alpha + ls;
      #pragma unroll
      for (int nt = 0; nt < 8; ++nt) {
        o[nt][2 * g] *= alpha;
        o[nt][2 * g + 1] *= alpha;
      }
    }

    // store P (tf32) into warp-private rows of Ps
    #pragma unroll
    for (int nt = 0; nt < 8; ++nt) {
      const int col = nt * 8 + lc * 2;
      Ps[qrow * 68 + col] = f2tf(sfr[nt][0]);
      Ps[qrow * 68 + col + 1] = f2tf(sfr[nt][1]);
      Ps[(qrow + 8) * 68 + col] = f2tf(sfr[nt][2]);
      Ps[(qrow + 8) * 68 + col + 1] = f2tf(sfr[nt][3]);
    }
    __syncwarp();  // warp produces & consumes its own P rows

    // O += P V
    #pragma unroll
    for (int kk = 0; kk < 8; ++kk) {
      uint32_t ap[4];
      const int c = kk * 8 + lc;
      ap[0] = Ps[qrow * 68 + c];
      ap[1] = Ps[(qrow + 8) * 68 + c];
      ap[2] = Ps[qrow * 68 + c + 4];
      ap[3] = Ps[(qrow + 8) * 68 + c + 4];
      const int kv = kk * 8 + lc;
      #pragma unroll
      for (int nt = 0; nt < 8; ++nt) {
        const int h = nt * 8 + lr;
        mma_tf32(o[nt], ap, f2tf(Vs[kv * 72 + h]),
                 f2tf(Vs[(kv + 4) * 72 + h]));
      }
    }

    __syncthreads();  // all warps done with stage s before it is re-filled
    issue(kt + 2);
  }

  // epilogue: normalize and store
  float* og = out + ((size_t)b * T + (size_t)qt * 64) * H;
  const float inv0 = 1.f / l[0], inv1 = 1.f / l[1];
  #pragma unroll
  for (int nt = 0; nt < 8; ++nt) {
    const int h = nt * 8 + lc * 2;
    *reinterpret_cast<float2*>(&og[(size_t)qrow * H + h]) =
        make_float2(o[nt][0] * inv0, o[nt][1] * inv0);
    *reinterpret_cast<float2*>(&og[(size_t)(qrow + 8) * H + h]) =
        make_float2(o[nt][2] * inv1, o[nt][3] * inv1);
  }
}

extern "C" void kernel_launch(void* const* d_in, const int* in_sizes, int n_in,
                              void* d_out, int out_size) {
  const float* x = (const float*)d_in[0];
  const float* Wq = (const float*)d_in[1];
  const float* Wk = (const float*)d_in[2];
  const float* Wv = (const float*)d_in[3];
  float* out = (float*)d_out;

  // Host-side attribute sets: not stream ops -> capture-safe, idempotent.
  cudaFuncSetAttribute(qkv_mma_kernel,
                       cudaFuncAttributeMaxDynamicSharedMemorySize,
                       QKV_SMEM_BYTES);
  cudaFuncSetAttribute(attn_mma_kernel,
                       cudaFuncAttributeMaxDynamicSharedMemorySize,
                       ATTN_SMEM_BYTES);

  qkv_mma_kernel<<<BT / 64, 128, QKV_SMEM_BYTES>>>(x, Wq, Wk, Wv);
  attn_mma_kernel<<<dim3(8, B), 128, ATTN_SMEM_BYTES>>>(out);
}

// round 16
// speedup vs baseline: 1.3543x; 1.3543x over previous
#include <cuda_runtime.h>
#include <cstdint>

namespace {
constexpr int B = 64, T = 512, C = 384, H = 64;
constexpr int BT = B * T;
}

// Scratch for projected q, k, v (fp32, [B*T, H] each). Static device arrays.
__device__ float g_q[BT * H];
__device__ float g_k[BT * H];
__device__ float g_v[BT * H];

// ---------------------------------------------------------------------------
// helpers
// ---------------------------------------------------------------------------
__device__ __forceinline__ uint32_t f2tf(float f) {
  uint32_t u;
  asm("cvt.rna.tf32.f32 %0, %1;" : "=r"(u) : "f"(f));
  return u;
}

// D = A(16x8,row) * B(8x8,col) + C, tf32 inputs, fp32 accum.
__device__ __forceinline__ void mma_tf32(float* d, const uint32_t* a,
                                         uint32_t b0, uint32_t b1) {
  asm("mma.sync.aligned.m16n8k8.row.col.f32.tf32.tf32.f32 "
      "{%0,%1,%2,%3}, {%4,%5,%6,%7}, {%8,%9}, {%0,%1,%2,%3};"
      : "+f"(d[0]), "+f"(d[1]), "+f"(d[2]), "+f"(d[3])
      : "r"(a[0]), "r"(a[1]), "r"(a[2]), "r"(a[3]), "r"(b0), "r"(b1));
}

__device__ __forceinline__ void cp_async16(uint32_t smem_byte,
                                           const void* gptr) {
  asm volatile("cp.async.ca.shared.global [%0], [%1], 16;\n" ::"r"(smem_byte),
               "l"(gptr));
}
#define CP_COMMIT() asm volatile("cp.async.commit_group;\n" ::: "memory")
#define CP_WAIT1() asm volatile("cp.async.wait_group 1;\n" ::: "memory")

__device__ __forceinline__ uint32_t smem_u32(const void* p) {
  return (uint32_t)__cvta_generic_to_shared(p);
}

// in-place fp32 -> tf32 conversion of one float4-aligned smem chunk
__device__ __forceinline__ void cvt4_inplace(float* p) {
  float4 v = *reinterpret_cast<float4*>(p);
  uint4 u;
  u.x = f2tf(v.x);
  u.y = f2tf(v.y);
  u.z = f2tf(v.z);
  u.w = f2tf(v.w);
  *reinterpret_cast<uint4*>(p) = u;
}

// ---------------------------------------------------------------------------
// Kernel 1: fused QKV projection, tf32 mma, cp.async 2-stage pipeline.
// y[32768,192] = x[32768,384] @ [Wq|Wk|Wv][384,192].
// CTA: 256 thr = 8 warps (4M x 2N), CTA tile 128x192, K-chunk 32, 12 chunks.
// Raw fp32 staged via cp.async; one vectorized in-place cvt pass per chunk;
// then the (R11-proven) clean tf32 mma loop.
// smem strides: xs=36 (≡4 mod 32), ws=200 (≡8 mod 32) -> conflict-free.
// ---------------------------------------------------------------------------
namespace {
constexpr int XS_STRIDE = 36;
constexpr int WS_STRIDE = 200;
constexpr int X_STAGE_W = 128 * XS_STRIDE;              // 4608 words
constexpr int W_STAGE_W = 32 * WS_STRIDE;               // 6400 words
constexpr int QKV_W_OFF = 2 * X_STAGE_W;                // 9216
constexpr int QKV_SMEM_W = QKV_W_OFF + 2 * W_STAGE_W;   // 22016
constexpr int QKV_SMEM_BYTES = QKV_SMEM_W * 4;          // 88064
}

__global__ __launch_bounds__(256, 2) void qkv_mma_kernel(
    const float* __restrict__ x, const float* __restrict__ Wq,
    const float* __restrict__ Wk, const float* __restrict__ Wv) {
  extern __shared__ float qsm[];
  const uint32_t smb = smem_u32(qsm);

  const int row0 = blockIdx.x * 128;
  const int warp = threadIdx.x >> 5;
  const int lane = threadIdx.x & 31;
  const int wm = warp >> 1;  // 0..3 -> rows wm*32..+32
  const int wn = warp & 1;   // 0..1 -> cols wn*96..+96
  const int lr = lane >> 2;  // 0..7
  const int lc = lane & 3;   // 0..3

  // issue cp.asyncs for one K-chunk into stage (chunk&1); always commit
  // (uniform commit count across all threads -> no wait_group divergence).
  auto issue = [&](int chunk) {
    if (chunk < 12) {
      const int s = chunk & 1;
      const int c0 = chunk * 32;
      // x tile [128 x 32]: 1024 float4 / 256 thr = 4 each
      const uint32_t xb = smb + (uint32_t)(s * X_STAGE_W) * 4u;
      #pragma unroll
      for (int i = threadIdx.x; i < 1024; i += 256) {
        const int r = i >> 3, c4 = i & 7;
        cp_async16(xb + (uint32_t)(r * XS_STRIDE + c4 * 4) * 4u,
                   x + (size_t)(row0 + r) * C + c0 + c4 * 4);
      }
      // W tile [32 x 192]: 1536 float4 / 256 thr = 6 each
      const uint32_t wb = smb + (uint32_t)(QKV_W_OFF + s * W_STAGE_W) * 4u;
      #pragma unroll
      for (int i = threadIdx.x; i < 1536; i += 256) {
        const int k = i / 48, n4 = i % 48;
        const float* Wsrc = (n4 < 16) ? Wq : (n4 < 32) ? Wk : Wv;
        cp_async16(wb + (uint32_t)(k * WS_STRIDE + n4 * 4) * 4u,
                   Wsrc + (size_t)(c0 + k) * H + (n4 & 15) * 4);
      }
    }
    CP_COMMIT();
  };

  float acc[2][12][4];
  #pragma unroll
  for (int mt = 0; mt < 2; ++mt)
    #pragma unroll
    for (int nt = 0; nt < 12; ++nt)
      #pragma unroll
      for (int i = 0; i < 4; ++i) acc[mt][nt][i] = 0.f;

  issue(0);
  issue(1);

  for (int chunk = 0; chunk < 12; ++chunk) {
    const int s = chunk & 1;
    CP_WAIT1();
    __syncthreads();

    float* Xf = qsm + s * X_STAGE_W;
    float* Wf = qsm + QKV_W_OFF + s * W_STAGE_W;

    // in-place cvt pass: x 1024 f4 + W 1536 f4 over 256 threads
    #pragma unroll
    for (int i = threadIdx.x; i < 1024; i += 256)
      cvt4_inplace(Xf + (i >> 3) * XS_STRIDE + (i & 7) * 4);
    #pragma unroll
    for (int i = threadIdx.x; i < 1536; i += 256)
      cvt4_inplace(Wf + (i / 48) * WS_STRIDE + (i % 48) * 4);
    __syncthreads();

    const uint32_t* Xs = reinterpret_cast<const uint32_t*>(Xf);
    const uint32_t* Ws = reinterpret_cast<const uint32_t*>(Wf);

    // A fragments (2 m-tiles x 4 k-steps)
    uint32_t af[2][4][4];
    #pragma unroll
    for (int mt = 0; mt < 2; ++mt) {
      const int row = wm * 32 + mt * 16 + lr;
      #pragma unroll
      for (int kk = 0; kk < 4; ++kk) {
        const int col = kk * 8 + lc;
        af[mt][kk][0] = Xs[row * XS_STRIDE + col];
        af[mt][kk][1] = Xs[(row + 8) * XS_STRIDE + col];
        af[mt][kk][2] = Xs[row * XS_STRIDE + col + 4];
        af[mt][kk][3] = Xs[(row + 8) * XS_STRIDE + col + 4];
      }
    }

    #pragma unroll
    for (int nt = 0; nt < 12; ++nt) {
      const int n = wn * 96 + nt * 8 + lr;
      #pragma unroll
      for (int kk = 0; kk < 4; ++kk) {
        const int k = kk * 8 + lc;
        const uint32_t b0 = Ws[k * WS_STRIDE + n];
        const uint32_t b1 = Ws[(k + 4) * WS_STRIDE + n];
        mma_tf32(acc[0][nt], af[0][kk], b0, b1);
        mma_tf32(acc[1][nt], af[1][kk], b0, b1);
      }
    }

    __syncthreads();  // stage s fully consumed before refill
    issue(chunk + 2);
  }

  // epilogue: scatter to g_q / g_k / g_v
  #pragma unroll
  for (int mt = 0; mt < 2; ++mt) {
    const int rbase = row0 + wm * 32 + mt * 16 + lr;
    #pragma unroll
    for (int nt = 0; nt < 12; ++nt) {
      const int n0 = wn * 96 + nt * 8 + lc * 2;
      float* dst = (n0 < 64) ? g_q : (n0 < 128) ? g_k : g_v;
      const int nn = n0 & 63;
      *reinterpret_cast<float2*>(&dst[(size_t)rbase * H + nn]) =
          make_float2(acc[mt][nt][0], acc[mt][nt][1]);
      *reinterpret_cast<float2*>(&dst[(size_t)(rbase + 8) * H + nn]) =
          make_float2(acc[mt][nt][2], acc[mt][nt][3]);
    }
  }
}

// ---------------------------------------------------------------------------
// Kernel 2: flash attention, causal, tf32 mma, cp.async 2-stage K/V pipeline
// with in-place cvt pass; mma loops are the R11-proven clean tf32 loops.
// Grid (8 qt, 64 b) x 128 thr. Warp w owns q-rows [w*16, w*16+16).
// Strides: Qs/Ks/Ps 68 (≡4 mod 32), Vs 72 (≡8 mod 32) -> conflict-free.
// ---------------------------------------------------------------------------
namespace {
constexpr int AQ_OFF = 0;                        // tf32 Q  [64][68]
constexpr int AK_OFF = 64 * 68;                  // K  2x[64][68]
constexpr int K_STAGE_W = 64 * 68;               // 4352
constexpr int AV_OFF = AK_OFF + 2 * K_STAGE_W;   // 13056: V 2x[64][72]
constexpr int V_STAGE_W = 64 * 72;               // 4608
constexpr int AP_OFF = AV_OFF + 2 * V_STAGE_W;   // 22272: tf32 P [64][68]
constexpr int ATTN_SMEM_W = AP_OFF + 64 * 68;    // 26624
constexpr int ATTN_SMEM_BYTES = ATTN_SMEM_W * 4; // 106496
}

__global__ __launch_bounds__(128, 2) void attn_mma_kernel(
    float* __restrict__ out) {
  extern __shared__ uint32_t sm[];
  uint32_t* Qs = sm + AQ_OFF;
  uint32_t* Ps = sm + AP_OFF;
  const uint32_t smb = smem_u32(sm);

  const int qt = 7 - (int)blockIdx.x;  // heavy tiles first
  const int b = (int)blockIdx.y;
  const int nkt = qt + 1;
  const int warp = threadIdx.x >> 5;
  const int lane = threadIdx.x & 31;
  const int lr = lane >> 2, lc = lane & 3;
  const int qrow = warp * 16 + lr;

  auto issue = [&](int kt) {
    if (kt < nkt) {
      const int s = kt & 1;
      const float* kg = g_k + ((size_t)b * T + (size_t)kt * 64) * H;
      const float* vg = g_v + ((size_t)b * T + (size_t)kt * 64) * H;
      const uint32_t kb = smb + (uint32_t)(AK_OFF + s * K_STAGE_W) * 4u;
      const uint32_t vb = smb + (uint32_t)(AV_OFF + s * V_STAGE_W) * 4u;
      #pragma unroll
      for (int i = threadIdx.x; i < 1024; i += 128) {
        const int r = i >> 4, c4 = i & 15;
        cp_async16(kb + (uint32_t)(r * 68 + c4 * 4) * 4u, kg + r * 64 + c4 * 4);
        cp_async16(vb + (uint32_t)(r * 72 + c4 * 4) * 4u, vg + r * 64 + c4 * 4);
      }
    }
    CP_COMMIT();
  };

  issue(0);
  issue(1);

  // stage Q (pre-scaled by 1/8), tf32 — overlaps with the cp.asyncs above
  const float* qg = g_q + ((size_t)b * T + (size_t)qt * 64) * H;
  for (int i = threadIdx.x * 4; i < 64 * 64; i += 512) {
    const float4 v = *reinterpret_cast<const float4*>(qg + i);
    const int r = i >> 6, c = i & 63;
    Qs[r * 68 + c] = f2tf(v.x * 0.125f);
    Qs[r * 68 + c + 1] = f2tf(v.y * 0.125f);
    Qs[r * 68 + c + 2] = f2tf(v.z * 0.125f);
    Qs[r * 68 + c + 3] = f2tf(v.w * 0.125f);
  }
  __syncthreads();

  // hoist Q A-fragments (8 k-steps x 4 regs)
  uint32_t aq[8][4];
  #pragma unroll
  for (int kk = 0; kk < 8; ++kk) {
    const int c = kk * 8 + lc;
    aq[kk][0] = Qs[qrow * 68 + c];
    aq[kk][1] = Qs[(qrow + 8) * 68 + c];
    aq[kk][2] = Qs[qrow * 68 + c + 4];
    aq[kk][3] = Qs[(qrow + 8) * 68 + c + 4];
  }

  float m[2] = {-1e30f, -1e30f}, l[2] = {0.f, 0.f};
  float o[8][4];
  #pragma unroll
  for (int nt = 0; nt < 8; ++nt)
    #pragma unroll
    for (int i = 0; i < 4; ++i) o[nt][i] = 0.f;

  for (int kt = 0; kt < nkt; ++kt) {
    const int s = kt & 1;
    CP_WAIT1();
    __syncthreads();

    float* Kf = reinterpret_cast<float*>(sm + AK_OFF + s * K_STAGE_W);
    float* Vf = reinterpret_cast<float*>(sm + AV_OFF + s * V_STAGE_W);

    // in-place cvt pass: K + V, 1024 f4 each over 128 threads
    #pragma unroll
    for (int i = threadIdx.x; i < 1024; i += 128) {
      const int r = i >> 4, c = (i & 15) * 4;
      cvt4_inplace(Kf + r * 68 + c);
      cvt4_inplace(Vf + r * 72 + c);
    }
    __syncthreads();

    const uint32_t* Ks = reinterpret_cast<const uint32_t*>(Kf);
    const uint32_t* Vs = reinterpret_cast<const uint32_t*>(Vf);

    // S = Q K^T
    float sfr[8][4];
    #pragma unroll
    for (int nt = 0; nt < 8; ++nt)
      #pragma unroll
      for (int i = 0; i < 4; ++i) sfr[nt][i] = 0.f;

    #pragma unroll
    for (int nt = 0; nt < 8; ++nt) {
      const int kv = nt * 8 + lr;
      #pragma unroll
      for (int kk = 0; kk < 8; ++kk) {
        const int h = kk * 8 + lc;
        mma_tf32(sfr[nt], aq[kk], Ks[kv * 68 + h], Ks[kv * 68 + h + 4]);
      }
    }

    if (kt == qt) {  // causal mask inside diagonal tile
      #pragma unroll
      for (int nt = 0; nt < 8; ++nt) {
        const int kv0 = nt * 8 + lc * 2;
        if (kv0 > qrow) sfr[nt][0] = -1e30f;
        if (kv0 + 1 > qrow) sfr[nt][1] = -1e30f;
        if (kv0 > qrow + 8) sfr[nt][2] = -1e30f;
        if (kv0 + 1 > qrow + 8) sfr[nt][3] = -1e30f;
      }
    }

    // online softmax per fragment row-group (rows qrow, qrow+8)
    #pragma unroll
    for (int g = 0; g < 2; ++g) {
      float mx = -1e30f;
      #pragma unroll
      for (int nt = 0; nt < 8; ++nt)
        mx = fmaxf(mx, fmaxf(sfr[nt][2 * g], sfr[nt][2 * g + 1]));
      mx = fmaxf(mx, __shfl_xor_sync(0xffffffffu, mx, 1));
      mx = fmaxf(mx, __shfl_xor_sync(0xffffffffu, mx, 2));
      const float mnew = fmaxf(m[g], mx);
      const float alpha = __expf(m[g] - mnew);
      float ls = 0.f;
      #pragma unroll
      for (int nt = 0; nt < 8; ++nt) {
        const float p0 = __expf(sfr[nt][2 * g] - mnew);
        const float p1 = __expf(sfr[nt][2 * g + 1] - mnew);
        sfr[nt][2 * g] = p0;
        sfr[nt][2 * g + 1] = p1;
        ls += p0 + p1;
      }
      ls += __shfl_xor_sync(0xffffffffu, ls, 1);
      ls += __shfl_xor_sync(0xffffffffu, ls, 2);
      m[g] = mnew;
      l[g] = l[g] * alpha + ls;
      #pragma unroll
      for (int nt = 0; nt < 8; ++nt) {
        o[nt][2 * g] *= alpha;
        o[nt][2 * g + 1] *= alpha;
      }
    }

    // store P (tf32) into warp-private rows of Ps
    #pragma unroll
    for (int nt = 0; nt < 8; ++nt) {
      const int col = nt * 8 + lc * 2;
      Ps[qrow * 68 + col] = f2tf(sfr[nt][0]);
      Ps[qrow * 68 + col + 1] = f2tf(sfr[nt][1]);
      Ps[(qrow + 8) * 68 + col] = f2tf(sfr[nt][2]);
      Ps[(qrow + 8) * 68 + col + 1] = f2tf(sfr[nt][3]);
    }
    __syncwarp();  // warp produces & consumes its own P rows

    // O += P V
    #pragma unroll
    for (int kk = 0; kk < 8; ++kk) {
      uint32_t ap[4];
      const int c = kk * 8 + lc;
      ap[0] = Ps[qrow * 68 + c];
      ap[1] = Ps[(qrow + 8) * 68 + c];
      ap[2] = Ps[qrow * 68 + c + 4];
      ap[3] = Ps[(qrow + 8) * 68 + c + 4];
      const int kv = kk * 8 + lc;
      #pragma unroll
      for (int nt = 0; nt < 8; ++nt) {
        const int h = nt * 8 + lr;
        mma_tf32(o[nt], ap, Vs[kv * 72 + h], Vs[(kv + 4) * 72 + h]);
      }
    }

    __syncthreads();  // all warps done with stage s before it is re-filled
    issue(kt + 2);
  }

  // epilogue: normalize and store
  float* og = out + ((size_t)b * T + (size_t)qt * 64) * H;
  const float inv0 = 1.f / l[0], inv1 = 1.f / l[1];
  #pragma unroll
  for (int nt = 0; nt < 8; ++nt) {
    const int h = nt * 8 + lc * 2;
    *reinterpret_cast<float2*>(&og[(size_t)qrow * H + h]) =
        make_float2(o[nt][0] * inv0, o[nt][1] * inv0);
    *reinterpret_cast<float2*>(&og[(size_t)(qrow + 8) * H + h]) =
        make_float2(o[nt][2] * inv1, o[nt][3] * inv1);
  }
}

extern "C" void kernel_launch(void* const* d_in, const int* in_sizes, int n_in,
                              void* d_out, int out_size) {
  const float* x = (const float*)d_in[0];
  const float* Wq = (const float*)d_in[1];
  const float* Wk = (const float*)d_in[2];
  const float* Wv = (const float*)d_in[3];
  float* out = (float*)d_out;

  // Host-side attribute sets: not stream ops -> capture-safe, idempotent.
  cudaFuncSetAttribute(qkv_mma_kernel,
                       cudaFuncAttributeMaxDynamicSharedMemorySize,
                       QKV_SMEM_BYTES);
  cudaFuncSetAttribute(attn_mma_kernel,
                       cudaFuncAttributeMaxDynamicSharedMemorySize,
                       ATTN_SMEM_BYTES);

  qkv_mma_kernel<<<BT / 128, 256, QKV_SMEM_BYTES>>>(x, Wq, Wk, Wv);
  attn_mma_kernel<<<dim3(8, B), 128, ATTN_SMEM_BYTES>>>(out);
}

// round 17
// speedup vs baseline: 1.3770x; 1.0168x over previous
#include <cuda_runtime.h>
#include <cstdint>

namespace {
constexpr int B = 64, T = 512, C = 384, H = 64;
constexpr int BT = B * T;
}

// Scratch for projected q, k, v (fp32, [B*T, H] each). Static device arrays.
__device__ float g_q[BT * H];
__device__ float g_k[BT * H];
__device__ float g_v[BT * H];

// ---------------------------------------------------------------------------
// helpers
// ---------------------------------------------------------------------------
__device__ __forceinline__ uint32_t f2tf(float f) {
  uint32_t u;
  asm("cvt.rna.tf32.f32 %0, %1;" : "=r"(u) : "f"(f));
  return u;
}

// D = A(16x8,row) * B(8x8,col) + C, tf32 inputs, fp32 accum.
__device__ __forceinline__ void mma_tf32(float* d, const uint32_t* a,
                                         uint32_t b0, uint32_t b1) {
  asm("mma.sync.aligned.m16n8k8.row.col.f32.tf32.tf32.f32 "
      "{%0,%1,%2,%3}, {%4,%5,%6,%7}, {%8,%9}, {%0,%1,%2,%3};"
      : "+f"(d[0]), "+f"(d[1]), "+f"(d[2]), "+f"(d[3])
      : "r"(a[0]), "r"(a[1]), "r"(a[2]), "r"(a[3]), "r"(b0), "r"(b1));
}

__device__ __forceinline__ void cp_async16(uint32_t smem_byte,
                                           const void* gptr) {
  asm volatile("cp.async.ca.shared.global [%0], [%1], 16;\n" ::"r"(smem_byte),
               "l"(gptr));
}
#define CP_COMMIT() asm volatile("cp.async.commit_group;\n" ::: "memory")
#define CP_WAIT1() asm volatile("cp.async.wait_group 1;\n" ::: "memory")
#define CP_WAIT2() asm volatile("cp.async.wait_group 2;\n" ::: "memory")

__device__ __forceinline__ uint32_t smem_u32(const void* p) {
  return (uint32_t)__cvta_generic_to_shared(p);
}

// in-place fp32 -> tf32 conversion of one float4-aligned smem chunk
__device__ __forceinline__ void cvt4_inplace(float* p) {
  float4 v = *reinterpret_cast<float4*>(p);
  uint4 u;
  u.x = f2tf(v.x);
  u.y = f2tf(v.y);
  u.z = f2tf(v.z);
  u.w = f2tf(v.w);
  *reinterpret_cast<uint4*>(p) = u;
}

// ---------------------------------------------------------------------------
// Kernel 1: fused QKV projection, tf32 mma, cp.async 2-stage pipeline.
// (Unchanged from R16 — proven at ~53 us.)
// ---------------------------------------------------------------------------
namespace {
constexpr int XS_STRIDE = 36;
constexpr int WS_STRIDE = 200;
constexpr int X_STAGE_W = 128 * XS_STRIDE;              // 4608 words
constexpr int W_STAGE_W = 32 * WS_STRIDE;               // 6400 words
constexpr int QKV_W_OFF = 2 * X_STAGE_W;                // 9216
constexpr int QKV_SMEM_W = QKV_W_OFF + 2 * W_STAGE_W;   // 22016
constexpr int QKV_SMEM_BYTES = QKV_SMEM_W * 4;          // 88064
}

__global__ __launch_bounds__(256, 2) void qkv_mma_kernel(
    const float* __restrict__ x, const float* __restrict__ Wq,
    const float* __restrict__ Wk, const float* __restrict__ Wv) {
  extern __shared__ float qsm[];
  const uint32_t smb = smem_u32(qsm);

  const int row0 = blockIdx.x * 128;
  const int warp = threadIdx.x >> 5;
  const int lane = threadIdx.x & 31;
  const int wm = warp >> 1;
  const int wn = warp & 1;
  const int lr = lane >> 2;
  const int lc = lane & 3;

  auto issue = [&](int chunk) {
    if (chunk < 12) {
      const int s = chunk & 1;
      const int c0 = chunk * 32;
      const uint32_t xb = smb + (uint32_t)(s * X_STAGE_W) * 4u;
      #pragma unroll
      for (int i = threadIdx.x; i < 1024; i += 256) {
        const int r = i >> 3, c4 = i & 7;
        cp_async16(xb + (uint32_t)(r * XS_STRIDE + c4 * 4) * 4u,
                   x + (size_t)(row0 + r) * C + c0 + c4 * 4);
      }
      const uint32_t wb = smb + (uint32_t)(QKV_W_OFF + s * W_STAGE_W) * 4u;
      #pragma unroll
      for (int i = threadIdx.x; i < 1536; i += 256) {
        const int k = i / 48, n4 = i % 48;
        const float* Wsrc = (n4 < 16) ? Wq : (n4 < 32) ? Wk : Wv;
        cp_async16(wb + (uint32_t)(k * WS_STRIDE + n4 * 4) * 4u,
                   Wsrc + (size_t)(c0 + k) * H + (n4 & 15) * 4);
      }
    }
    CP_COMMIT();
  };

  float acc[2][12][4];
  #pragma unroll
  for (int mt = 0; mt < 2; ++mt)
    #pragma unroll
    for (int nt = 0; nt < 12; ++nt)
      #pragma unroll
      for (int i = 0; i < 4; ++i) acc[mt][nt][i] = 0.f;

  issue(0);
  issue(1);

  for (int chunk = 0; chunk < 12; ++chunk) {
    const int s = chunk & 1;
    CP_WAIT1();
    __syncthreads();

    float* Xf = qsm + s * X_STAGE_W;
    float* Wf = qsm + QKV_W_OFF + s * W_STAGE_W;

    #pragma unroll
    for (int i = threadIdx.x; i < 1024; i += 256)
      cvt4_inplace(Xf + (i >> 3) * XS_STRIDE + (i & 7) * 4);
    #pragma unroll
    for (int i = threadIdx.x; i < 1536; i += 256)
      cvt4_inplace(Wf + (i / 48) * WS_STRIDE + (i % 48) * 4);
    __syncthreads();

    const uint32_t* Xs = reinterpret_cast<const uint32_t*>(Xf);
    const uint32_t* Ws = reinterpret_cast<const uint32_t*>(Wf);

    uint32_t af[2][4][4];
    #pragma unroll
    for (int mt = 0; mt < 2; ++mt) {
      const int row = wm * 32 + mt * 16 + lr;
      #pragma unroll
      for (int kk = 0; kk < 4; ++kk) {
        const int col = kk * 8 + lc;
        af[mt][kk][0] = Xs[row * XS_STRIDE + col];
        af[mt][kk][1] = Xs[(row + 8) * XS_STRIDE + col];
        af[mt][kk][2] = Xs[row * XS_STRIDE + col + 4];
        af[mt][kk][3] = Xs[(row + 8) * XS_STRIDE + col + 4];
      }
    }

    #pragma unroll
    for (int nt = 0; nt < 12; ++nt) {
      const int n = wn * 96 + nt * 8 + lr;
      #pragma unroll
      for (int kk = 0; kk < 4; ++kk) {
        const int k = kk * 8 + lc;
        const uint32_t b0 = Ws[k * WS_STRIDE + n];
        const uint32_t b1 = Ws[(k + 4) * WS_STRIDE + n];
        mma_tf32(acc[0][nt], af[0][kk], b0, b1);
        mma_tf32(acc[1][nt], af[1][kk], b0, b1);
      }
    }

    __syncthreads();
    issue(chunk + 2);
  }

  #pragma unroll
  for (int mt = 0; mt < 2; ++mt) {
    const int rbase = row0 + wm * 32 + mt * 16 + lr;
    #pragma unroll
    for (int nt = 0; nt < 12; ++nt) {
      const int n0 = wn * 96 + nt * 8 + lc * 2;
      float* dst = (n0 < 64) ? g_q : (n0 < 128) ? g_k : g_v;
      const int nn = n0 & 63;
      *reinterpret_cast<float2*>(&dst[(size_t)rbase * H + nn]) =
          make_float2(acc[mt][nt][0], acc[mt][nt][1]);
      *reinterpret_cast<float2*>(&dst[(size_t)(rbase + 8) * H + nn]) =
          make_float2(acc[mt][nt][2], acc[mt][nt][3]);
    }
  }
}

// ---------------------------------------------------------------------------
// Kernel 2: flash attention, causal, tf32 mma.
// R17 changes vs R16: (a) Ps buffer removed — PV A-fragments built from the
// softmax C-fragments by warp shuffle transpose; (b) V single-buffered with
// separate K/V commit groups. smem 106.5KB -> 70.7KB => 3 CTAs/SM.
// Strides: Qs/Ks 68 (≡4 mod 32), Vs 72 (≡8 mod 32) -> conflict-free.
// ---------------------------------------------------------------------------
namespace {
constexpr int AQ_OFF = 0;                        // tf32 Q [64][68]
constexpr int AK_OFF = 64 * 68;                  // K 2x[64][68]
constexpr int K_STAGE_W = 64 * 68;               // 4352
constexpr int AV_OFF = AK_OFF + 2 * K_STAGE_W;   // 13056: V 1x[64][72]
constexpr int ATTN_SMEM_W = AV_OFF + 64 * 72;    // 17664
constexpr int ATTN_SMEM_BYTES = ATTN_SMEM_W * 4; // 70656
}

__global__ __launch_bounds__(128, 3) void attn_mma_kernel(
    float* __restrict__ out) {
  extern __shared__ uint32_t sm[];
  uint32_t* Qs = sm + AQ_OFF;
  const uint32_t smb = smem_u32(sm);

  const int qt = 7 - (int)blockIdx.x;  // heavy tiles first
  const int b = (int)blockIdx.y;
  const int nkt = qt + 1;
  const int warp = threadIdx.x >> 5;
  const int lane = threadIdx.x & 31;
  const int lr = lane >> 2, lc = lane & 3;
  const int qrow = warp * 16 + lr;
  const int psrc0 = (lane & ~3) | (lc >> 1);  // shuffle src for P cols j=lc
  const int psrc2 = psrc0 + 2;                // for P cols j=lc+4
  const bool podd = (lc & 1) != 0;

  // separate commit groups for K and V (uniform commit count all threads)
  auto issue_k = [&](int kt) {
    if (kt < nkt) {
      const int s = kt & 1;
      const float* kg = g_k + ((size_t)b * T + (size_t)kt * 64) * H;
      const uint32_t kb = smb + (uint32_t)(AK_OFF + s * K_STAGE_W) * 4u;
      #pragma unroll
      for (int i = threadIdx.x; i < 1024; i += 128) {
        const int r = i >> 4, c4 = i & 15;
        cp_async16(kb + (uint32_t)(r * 68 + c4 * 4) * 4u, kg + r * 64 + c4 * 4);
      }
    }
    CP_COMMIT();
  };
  auto issue_v = [&](int kt) {
    if (kt < nkt) {
      const float* vg = g_v + ((size_t)b * T + (size_t)kt * 64) * H;
      const uint32_t vb = smb + (uint32_t)AV_OFF * 4u;
      #pragma unroll
      for (int i = threadIdx.x; i < 1024; i += 128) {
        const int r = i >> 4, c4 = i & 15;
        cp_async16(vb + (uint32_t)(r * 72 + c4 * 4) * 4u, vg + r * 64 + c4 * 4);
      }
    }
    CP_COMMIT();
  };

  // ledger: g0=K0, g1=V0, g2=K1; per iter: WAIT2 -> K(kt), WAIT1 -> V(kt);
  // end of iter commits V(kt+1), K(kt+2).
  issue_k(0);
  issue_v(0);
  issue_k(1);

  // stage Q (pre-scaled by 1/8), tf32 — overlaps with the cp.asyncs above
  const float* qg = g_q + ((size_t)b * T + (size_t)qt * 64) * H;
  for (int i = threadIdx.x * 4; i < 64 * 64; i += 512) {
    const float4 v = *reinterpret_cast<const float4*>(qg + i);
    const int r = i >> 6, c = i & 63;
    Qs[r * 68 + c] = f2tf(v.x * 0.125f);
    Qs[r * 68 + c + 1] = f2tf(v.y * 0.125f);
    Qs[r * 68 + c + 2] = f2tf(v.z * 0.125f);
    Qs[r * 68 + c + 3] = f2tf(v.w * 0.125f);
  }
  __syncthreads();

  // hoist Q A-fragments (8 k-steps x 4 regs)
  uint32_t aq[8][4];
  #pragma unroll
  for (int kk = 0; kk < 8; ++kk) {
    const int c = kk * 8 + lc;
    aq[kk][0] = Qs[qrow * 68 + c];
    aq[kk][1] = Qs[(qrow + 8) * 68 + c];
    aq[kk][2] = Qs[qrow * 68 + c + 4];
    aq[kk][3] = Qs[(qrow + 8) * 68 + c + 4];
  }

  float m[2] = {-1e30f, -1e30f}, l[2] = {0.f, 0.f};
  float o[8][4];
  #pragma unroll
  for (int nt = 0; nt < 8; ++nt)
    #pragma unroll
    for (int i = 0; i < 4; ++i) o[nt][i] = 0.f;

  for (int kt = 0; kt < nkt; ++kt) {
    const int s = kt & 1;

    // ---- K(kt) ready ----
    CP_WAIT2();
    __syncthreads();
    float* Kf = reinterpret_cast<float*>(sm + AK_OFF + s * K_STAGE_W);
    #pragma unroll
    for (int i = threadIdx.x; i < 1024; i += 128)
      cvt4_inplace(Kf + (i >> 4) * 68 + (i & 15) * 4);
    __syncthreads();
    const uint32_t* Ks = reinterpret_cast<const uint32_t*>(Kf);

    // S = Q K^T
    float sfr[8][4];
    #pragma unroll
    for (int nt = 0; nt < 8; ++nt)
      #pragma unroll
      for (int i = 0; i < 4; ++i) sfr[nt][i] = 0.f;

    #pragma unroll
    for (int nt = 0; nt < 8; ++nt) {
      const int kv = nt * 8 + lr;
      #pragma unroll
      for (int kk = 0; kk < 8; ++kk) {
        const int h = kk * 8 + lc;
        mma_tf32(sfr[nt], aq[kk], Ks[kv * 68 + h], Ks[kv * 68 + h + 4]);
      }
    }

    if (kt == qt) {  // causal mask inside diagonal tile
      #pragma unroll
      for (int nt = 0; nt < 8; ++nt) {
        const int kv0 = nt * 8 + lc * 2;
        if (kv0 > qrow) sfr[nt][0] = -1e30f;
        if (kv0 + 1 > qrow) sfr[nt][1] = -1e30f;
        if (kv0 > qrow + 8) sfr[nt][2] = -1e30f;
        if (kv0 + 1 > qrow + 8) sfr[nt][3] = -1e30f;
      }
    }

    // online softmax per fragment row-group (rows qrow, qrow+8)
    #pragma unroll
    for (int g = 0; g < 2; ++g) {
      float mx = -1e30f;
      #pragma unroll
      for (int nt = 0; nt < 8; ++nt)
        mx = fmaxf(mx, fmaxf(sfr[nt][2 * g], sfr[nt][2 * g + 1]));
      mx = fmaxf(mx, __shfl_xor_sync(0xffffffffu, mx, 1));
      mx = fmaxf(mx, __shfl_xor_sync(0xffffffffu, mx, 2));
      const float mnew = fmaxf(m[g], mx);
      const float alpha = __expf(m[g] - mnew);
      float ls = 0.f;
      #pragma unroll
      for (int nt = 0; nt < 8; ++nt) {
        const float p0 = __expf(sfr[nt][2 * g] - mnew);
        const float p1 = __expf(sfr[nt][2 * g + 1] - mnew);
        sfr[nt][2 * g] = p0;
        sfr[nt][2 * g + 1] = p1;
        ls += p0 + p1;
      }
      ls += __shfl_xor_sync(0xffffffffu, ls, 1);
      ls += __shfl_xor_sync(0xffffffffu, ls, 2);
      m[g] = mnew;
      l[g] = l[g] * alpha + ls;
      #pragma unroll
      for (int nt = 0; nt < 8; ++nt) {
        o[nt][2 * g] *= alpha;
        o[nt][2 * g + 1] *= alpha;
      }
    }

    // ---- V(kt) ready ----
    CP_WAIT1();
    __syncthreads();
    float* Vf = reinterpret_cast<float*>(sm + AV_OFF);
    #pragma unroll
    for (int i = threadIdx.x; i < 1024; i += 128)
      cvt4_inplace(Vf + (i >> 4) * 72 + (i & 15) * 4);
    __syncthreads();
    const uint32_t* Vs = reinterpret_cast<const uint32_t*>(Vf);

    // O += P V.  P A-fragments built from sfr (C-layout) via shuffle
    // transpose: P(row base+8*rg, col kk*8+j) lives in lane (lr, j>>1),
    // element 2*rg + (j&1).
    #pragma unroll
    for (int kk = 0; kk < 8; ++kk) {
      const float a0 = __shfl_sync(0xffffffffu, sfr[kk][0], psrc0);
      const float a1 = __shfl_sync(0xffffffffu, sfr[kk][1], psrc0);
      const float a2 = __shfl_sync(0xffffffffu, sfr[kk][2], psrc0);
      const float a3 = __shfl_sync(0xffffffffu, sfr[kk][3], psrc0);
      const float c0 = __shfl_sync(0xffffffffu, sfr[kk][0], psrc2);
      const float c1 = __shfl_sync(0xffffffffu, sfr[kk][1], psrc2);
      const float c2 = __shfl_sync(0xffffffffu, sfr[kk][2], psrc2);
      const float c3 = __shfl_sync(0xffffffffu, sfr[kk][3], psrc2);
      uint32_t ap[4];
      ap[0] = f2tf(podd ? a1 : a0);  // (qrow,   kk*8+lc)
      ap[1] = f2tf(podd ? a3 : a2);  // (qrow+8, kk*8+lc)
      ap[2] = f2tf(podd ? c1 : c0);  // (qrow,   kk*8+lc+4)
      ap[3] = f2tf(podd ? c3 : c2);  // (qrow+8, kk*8+lc+4)
      const int kv = kk * 8 + lc;
      #pragma unroll
      for (int nt = 0; nt < 8; ++nt) {
        const int h = nt * 8 + lr;
        mma_tf32(o[nt], ap, Vs[kv * 72 + h], Vs[(kv + 4) * 72 + h]);
      }
    }

    __syncthreads();  // V stage + K stage s fully consumed before refill
    issue_v(kt + 1);
    issue_k(kt + 2);
  }

  // epilogue: normalize and store
  float* og = out + ((size_t)b * T + (size_t)qt * 64) * H;
  const float inv0 = 1.f / l[0], inv1 = 1.f / l[1];
  #pragma unroll
  for (int nt = 0; nt < 8; ++nt) {
    const int h = nt * 8 + lc * 2;
    *reinterpret_cast<float2*>(&og[(size_t)qrow * H + h]) =
        make_float2(o[nt][0] * inv0, o[nt][1] * inv0);
    *reinterpret_cast<float2*>(&og[(size_t)(qrow + 8) * H + h]) =
        make_float2(o[nt][2] * inv1, o[nt][3] * inv1);
  }
}

extern "C" void kernel_launch(void* const* d_in, const int* in_sizes, int n_in,
                              void* d_out, int out_size) {
  const float* x = (const float*)d_in[0];
  const float* Wq = (const float*)d_in[1];
  const float* Wk = (const float*)d_in[2];
  const float* Wv = (const float*)d_in[3];
  float* out = (float*)d_out;

  // Host-side attribute sets: not stream ops -> capture-safe, idempotent.
  cudaFuncSetAttribute(qkv_mma_kernel,
                       cudaFuncAttributeMaxDynamicSharedMemorySize,
                       QKV_SMEM_BYTES);
  cudaFuncSetAttribute(attn_mma_kernel,
                       cudaFuncAttributeMaxDynamicSharedMemorySize,
                       ATTN_SMEM_BYTES);

  qkv_mma_kernel<<<BT / 128, 256, QKV_SMEM_BYTES>>>(x, Wq, Wk, Wv);
  attn_mma_kernel<<<dim3(8, B), 128, ATTN_SMEM_BYTES>>>(out);
}